// round 9
// baseline (speedup 1.0000x reference)
#include <cuda_runtime.h>
#include <float.h>

#define N_COLS   32000
#define NV4      8000
#define THREADS  256
#define NWARPS   8
#define CAPC     16         // per-thread pruned-candidate slots (pow2)
#define FLATCAP  3072
#define NEWTON   12
#define MAX_ROWS 4096

__device__ float g_row_loss[MAX_ROWS];
__device__ unsigned g_done = 0;

__device__ __forceinline__ float max4(float4 v) {
    return fmaxf(fmaxf(v.x, v.y), fmaxf(v.z, v.w));
}

__global__ void __launch_bounds__(THREADS)
entmax15_fused(const float* __restrict__ inp, const int* __restrict__ tgt,
               float* __restrict__ out, int rows) {
    __shared__ unsigned char idxs[8 * THREADS];     // 2 KB: accepted group ids
    __shared__ float scand[CAPC * THREADS];         // 16 KB: per-thread pruned v
    __shared__ float flat[FLATCAP];                 // 12 KB: block candidate list (X units)
    __shared__ float redf[NWARPS];
    __shared__ float redA[NWARPS], redB[NWARPS], redC[NWARPS];
    __shared__ int   scnt[NWARPS];
    __shared__ int   iflags;
    __shared__ int   s_last;

    const int row  = blockIdx.x;
    const int tid  = threadIdx.x;
    const int lane = tid & 31;
    const int w    = tid >> 5;
    const float* rp = inp + (size_t)row * N_COLS;
    const float4* g4 = (const float4*)rp;

    // target logit (only tid 0 ever uses it)
    float tgl = 0.0f;
    if (tid == 0) {
        iflags = 0;
        int ti = tgt[row];
        ti = (ti < 0) ? 0 : ((ti >= N_COLS) ? N_COLS - 1 : ti);
        tgl = __ldg(rp + ti);
    }

    // ---- Phase A: groups 0..2 (12288 elems), keep per-group maxes ----
    float gmA0, gmA1, gmA2;
    {
        float4 a = g4[tid],        b = g4[tid + 256],  c = g4[tid + 512],  d = g4[tid + 768];
        gmA0 = fmaxf(fmaxf(max4(a), max4(b)), fmaxf(max4(c), max4(d)));
        float4 e = g4[tid + 1024], f = g4[tid + 1280], g = g4[tid + 1536], h = g4[tid + 1792];
        gmA1 = fmaxf(fmaxf(max4(e), max4(f)), fmaxf(max4(g), max4(h)));
        float4 i = g4[tid + 2048], j = g4[tid + 2304], k = g4[tid + 2560], l = g4[tid + 2816];
        gmA2 = fmaxf(fmaxf(max4(i), max4(j)), fmaxf(max4(k), max4(l)));
    }
    float lmax = fmaxf(fmaxf(gmA0, gmA1), gmA2);
    float e0 = lmax;
    #pragma unroll
    for (int o = 16; o; o >>= 1) e0 = fmaxf(e0, __shfl_xor_sync(0xffffffffu, e0, o));
    if (lane == 0) redf[w] = e0;
    __syncthreads();
    float m0 = redf[0];
    #pragma unroll
    for (int k = 1; k < NWARPS; ++k) m0 = fmaxf(m0, redf[k]);
    __syncthreads();
    const float thr = m0 - 2.0f;   // safe: m0 <= m => all true-support groups accepted

    // ---- Stash phase-A groups, then stream groups 3..7 ----
    int cnt = 0;
    idxs[((cnt & 7) << 8) + tid] = 0; cnt += (gmA0 >= thr);
    idxs[((cnt & 7) << 8) + tid] = 1; cnt += (gmA1 >= thr);
    idxs[((cnt & 7) << 8) + tid] = 2; cnt += (gmA2 >= thr);

    #pragma unroll
    for (int g = 3; g < 7; ++g) {
        int b0 = g * 1024 + tid;
        float4 a = g4[b0], b = g4[b0 + 256], c = g4[b0 + 512], d = g4[b0 + 768];
        float gm = fmaxf(fmaxf(max4(a), max4(b)), fmaxf(max4(c), max4(d)));
        lmax = fmaxf(lmax, gm);
        idxs[((cnt & 7) << 8) + tid] = (unsigned char)g;
        cnt += (gm >= thr);
    }
    {   // group 7: 3 full float4 + 4th only for tid < 64
        int b0 = 7 * 1024 + tid;
        float4 a = g4[b0], b = g4[b0 + 256], c = g4[b0 + 512];
        float4 d = g4[7936 + (tid & 63)];
        float gm = fmaxf(fmaxf(max4(a), max4(b)), max4(c));
        float dm = max4(d);
        gm = fmaxf(gm, (tid < 64) ? dm : -FLT_MAX);
        lmax = fmaxf(lmax, gm);
        idxs[((cnt & 7) << 8) + tid] = 7;
        cnt += (gm >= thr);
    }

    // ---- Exact row max ----
    float wm = lmax;
    #pragma unroll
    for (int o = 16; o; o >>= 1) wm = fmaxf(wm, __shfl_xor_sync(0xffffffffu, wm, o));
    if (lane == 0) redf[w] = wm;
    __syncthreads();
    float m = redf[0];
    #pragma unroll
    for (int k = 1; k < NWARPS; ++k) m = fmaxf(m, redf[k]);
    __syncthreads();

    // ---- Prune accepted groups to true candidates (raw v >= m-2), branch-free ----
    const float vthr = m - 2.0f;
    const float cm   = -0.5f * m;
    int kc = 0;
    #define PRUNE1(vv, ok) do { \
        bool _p = (ok) && ((vv) >= vthr); \
        if (_p) scand[((kc & (CAPC - 1)) << 8) + tid] = (vv); \
        kc += _p; } while (0)

    for (int j = 0; j < cnt; ++j) {
        int g = idxs[(j << 8) + tid];
        int b0 = g * 1024 + tid;
        float4 a = g4[b0], b = g4[b0 + 256], c = g4[b0 + 512];
        bool f4 = (g < 7) | (tid < 64);
        float4 d = g4[g * 1024 + 768 + ((g == 7) ? (tid & 63) : tid)];
        PRUNE1(a.x, true); PRUNE1(a.y, true); PRUNE1(a.z, true); PRUNE1(a.w, true);
        PRUNE1(b.x, true); PRUNE1(b.y, true); PRUNE1(b.z, true); PRUNE1(b.w, true);
        PRUNE1(c.x, true); PRUNE1(c.y, true); PRUNE1(c.z, true); PRUNE1(c.w, true);
        PRUNE1(d.x, f4);   PRUNE1(d.y, f4);   PRUNE1(d.z, f4);   PRUNE1(d.w, f4);
    }
    #undef PRUNE1

    // ---- Block exclusive prefix of kc -> flat positions ----
    int ws = kc;
    #pragma unroll
    for (int o = 1; o < 32; o <<= 1) {
        int t = __shfl_up_sync(0xffffffffu, ws, o);
        if (lane >= o) ws += t;
    }
    if (lane == 31) scnt[w] = ws;
    unsigned ob = __ballot_sync(0xffffffffu, kc > CAPC);
    if (lane == 0 && ob) atomicOr(&iflags, 1);
    __syncthreads();
    int base = 0, total = 0;
    #pragma unroll
    for (int q = 0; q < NWARPS; ++q) {
        int c = scnt[q];
        if (q < w) base += c;
        total += c;
    }
    base += ws - kc;
    const bool ovf = (total > FLATCAP) || (iflags != 0);

    if (!ovf) {
        for (int j = 0; j < kc; ++j)
            flat[base + j] = fmaf(scand[(j << 8) + tid], 0.5f, cm);   // X = (v-m)/2
    }
    __syncthreads();

    if (!ovf) {
        // ---- Warp 0 alone: Newton on flat list (shfl-only, no barriers) ----
        if (w == 0) {
            float tau = -1.0f;
            for (int it = 0; it < NEWTON; ++it) {
                float s1 = 0.0f, s2 = 0.0f;
                for (int i = lane; i < total; i += 32) {
                    float d = fmaxf(flat[i] - tau, 0.0f);
                    s1 += d; s2 = fmaf(d, d, s2);
                }
                #pragma unroll
                for (int o = 16; o; o >>= 1) {
                    s1 += __shfl_xor_sync(0xffffffffu, s1, o);
                    s2 += __shfl_xor_sync(0xffffffffu, s2, o);
                }
                tau += (s2 - 1.0f) / (2.0f * s1);   // monotone from below (f convex)
            }
            float sp = 0.0f, s15 = 0.0f, spx = 0.0f;
            for (int i = lane; i < total; i += 32) {
                float x = flat[i];
                float d = fmaxf(x - tau, 0.0f);
                float p = d * d;
                sp += p; s15 = fmaf(p, d, s15); spx = fmaf(p, x, spx);
            }
            #pragma unroll
            for (int o = 16; o; o >>= 1) {
                sp  += __shfl_xor_sync(0xffffffffu, sp,  o);
                s15 += __shfl_xor_sync(0xffffffffu, s15, o);
                spx += __shfl_xor_sync(0xffffffffu, spx, o);
            }
            if (lane == 0) {
                float omega = (1.0f - s15) * (4.0f / 3.0f);
                g_row_loss[row] = omega + 2.0f * spx + m * sp - tgl;
            }
        }
    } else {
        // ---- Fallback (rare: very low row max): block Newton over GMEM row ----
        float tau = -1.0f;
        for (int it = 0; it < 14; ++it) {
            float s1 = 0.0f, s2 = 0.0f;
            for (int q = tid; q < NV4; q += THREADS) {
                float4 v = g4[q];
                float xs[4] = {v.x, v.y, v.z, v.w};
                #pragma unroll
                for (int c = 0; c < 4; ++c) {
                    float d = fmaxf(fmaf(xs[c], 0.5f, cm) - tau, 0.0f);
                    s1 += d; s2 = fmaf(d, d, s2);
                }
            }
            #pragma unroll
            for (int o = 16; o; o >>= 1) {
                s1 += __shfl_xor_sync(0xffffffffu, s1, o);
                s2 += __shfl_xor_sync(0xffffffffu, s2, o);
            }
            if (lane == 0) { redA[w] = s1; redB[w] = s2; }
            __syncthreads();
            float S1 = 0.0f, S2 = 0.0f;
            #pragma unroll
            for (int k = 0; k < NWARPS; ++k) { S1 += redA[k]; S2 += redB[k]; }
            __syncthreads();
            tau += (S2 - 1.0f) / (2.0f * S1);
        }
        float sp = 0.0f, s15 = 0.0f, spx = 0.0f;
        for (int q = tid; q < NV4; q += THREADS) {
            float4 v = g4[q];
            float xs[4] = {v.x, v.y, v.z, v.w};
            #pragma unroll
            for (int c = 0; c < 4; ++c) {
                float x = fmaf(xs[c], 0.5f, cm);
                float d = fmaxf(x - tau, 0.0f);
                float p = d * d;
                sp += p; s15 = fmaf(p, d, s15); spx = fmaf(p, x, spx);
            }
        }
        #pragma unroll
        for (int o = 16; o; o >>= 1) {
            sp  += __shfl_xor_sync(0xffffffffu, sp,  o);
            s15 += __shfl_xor_sync(0xffffffffu, s15, o);
            spx += __shfl_xor_sync(0xffffffffu, spx, o);
        }
        if (lane == 0) { redA[w] = sp; redB[w] = s15; redC[w] = spx; }
        __syncthreads();
        if (tid == 0) {
            float SP = 0, S15 = 0, SPX = 0;
            #pragma unroll
            for (int k = 0; k < NWARPS; ++k) { SP += redA[k]; S15 += redB[k]; SPX += redC[k]; }
            float omega = (1.0f - S15) * (4.0f / 3.0f);
            g_row_loss[row] = omega + 2.0f * SPX + m * SP - tgl;
        }
    }

    // ---- Completion: last block computes the mean (deterministic) ----
    if (tid == 0) {
        __threadfence();
        unsigned old = atomicAdd(&g_done, 1u);
        s_last = (old == (unsigned)gridDim.x - 1u);
    }
    __syncthreads();
    if (s_last) {
        __threadfence();
        __shared__ float sred[THREADS];
        float v = 0.0f;
        for (int i = tid; i < rows; i += THREADS) v += g_row_loss[i];  // fixed order
        sred[tid] = v;
        __syncthreads();
        #pragma unroll
        for (int st = THREADS / 2; st; st >>= 1) {
            if (tid < st) sred[tid] += sred[tid + st];
            __syncthreads();
        }
        if (tid == 0) {
            out[0] = sred[0] / (float)rows;
            g_done = 0;   // reset for next graph replay
        }
    }
}

extern "C" void kernel_launch(void* const* d_in, const int* in_sizes, int n_in,
                              void* d_out, int out_size) {
    const float* inp = (const float*)d_in[0];
    const int*   tgt = (const int*)d_in[1];
    float*       out = (float*)d_out;
    const int rows = in_sizes[1];  // 4096

    entmax15_fused<<<rows, THREADS>>>(inp, tgt, out, rows);
}